// round 3
// baseline (speedup 1.0000x reference)
#include <cuda_runtime.h>
#include <math.h>

// Problem constants
#define S_TOK 8192
#define MDIM  4096
#define NEXP  64
#define CAP   128
#define SEC   67108864ULL            // S*E*C
#define OUT_FLOATS 134217793ULL      // 1 + 2*SEC + 64
#define ZMAIN 134217728ULL           // floats zeroed by main pattern
#define ZVEC  33554432u              // float4 count of main pattern

// GEMM tiling
#define TILE_M 128                   // tokens per CTA
#define KB     32
#define KSPLIT 2
#define KCHUNK (MDIM / KSPLIT)       // 2048
#define NSTEP  (KCHUNK / KB)         // 64
#define NTB    (S_TOK / TILE_M)      // 64 token blocks
#define GRID_G (NTB * KSPLIT)        // 128 CTAs (1 per SM, balanced)
#define CTHR   512                   // compute threads
#define ZTHR   128                   // dedicated zero-store threads
#define THREADS (CTHR + ZTHR)        // 640
#define LDA 132                      // padded smem strides (floats)
#define LDB 68

#define NZT (GRID_G * ZTHR)          // 16384 zero threads total
#define ZPT (ZVEC / NZT)             // 2048 float4 per zero thread

#define NBLK64 (S_TOK / 64)          // 128 blocks for gate/scatter

typedef unsigned long long u64;

// ---------- scratch (device globals; fully overwritten each launch) ----------
__device__ float g_part[KSPLIT * S_TOK * NEXP];   // 4 MB partial logits
__device__ int   g_eid[S_TOK];
__device__ float g_gate[S_TOK];
__device__ float g_me[NBLK64 * NEXP];
__device__ int   g_cnt[NBLK64 * NEXP];
__device__ int   g_offs[NBLK64 * NEXP];

// packed f32x2 FMA (PTX-only; ptxas never auto-fuses)
__device__ __forceinline__ void ffma2(u64& d, u64 a, u64 b) {
    asm("fma.rn.f32x2 %0, %1, %2, %0;" : "+l"(d) : "l"(a), "l"(b));
}
__device__ __forceinline__ u64 dup2(float b) {
    u64 r; unsigned u = __float_as_uint(b);
    asm("mov.b64 %0, {%1, %1};" : "=l"(r) : "r"(u));
    return r;
}
__device__ __forceinline__ void barc() {   // compute-warps-only barrier
    asm volatile("bar.sync 1, %0;" :: "n"(CTHR) : "memory");
}

// ---------------------------------------------------------------------------
// Kernel 1: warp-specialized. Warps 0-15: 128x64 fp32 GEMM over a K/2 chunk
// (FFMA2 inner loop). Warps 16-19: stream-zero the 537MB output buffer.
// ---------------------------------------------------------------------------
__global__ __launch_bounds__(THREADS) void gemm_zero_kernel(
    const float* __restrict__ x, const float* __restrict__ wg,
    float* __restrict__ out)
{
    __shared__ float sA[KB * LDA];
    __shared__ float sB[KB * LDB];

    const int t  = threadIdx.x;
    const int bx = blockIdx.x;

    if (t >= CTHR) {
        // ---------------- zero-store warps ----------------
        const unsigned zt  = t - CTHR;              // 0..127
        const unsigned zid = bx * ZTHR + zt;        // 0..16383
        float4* out4 = (float4*)out;
        const float4 z = make_float4(0.f, 0.f, 0.f, 0.f);
        #pragma unroll 8
        for (unsigned j = 0; j < ZPT; j++)
            out4[(size_t)j * NZT + zid] = z;
        // tail (last 65 floats)
        if (bx == 0 && zt < (unsigned)(OUT_FLOATS - ZMAIN))
            out[ZMAIN + zt] = 0.0f;
        return;
    }

    // ---------------- compute warps ----------------
    const int tb = bx & (NTB - 1);     // token block
    const int kh = bx >> 6;            // k chunk
    const int tx = t & 15;             // col group: 4 experts
    const int ty = t >> 4;             // row group: 4 tokens (2 u64 pairs)

    u64 acc[2][4];
    #pragma unroll
    for (int i = 0; i < 2; i++)
        #pragma unroll
        for (int j = 0; j < 4; j++) acc[i][j] = 0ULL;

    const float* xblk = x  + (size_t)tb * TILE_M * MDIM + (size_t)kh * KCHUNK;
    const float* wblk = wg + (size_t)kh * KCHUNK;

    // staging assignments
    const int arow0 = t >> 3;          // with id=t+512: +64
    const int ac    = (t & 7) * 4;
    const int brow  = t >> 3;          // 0..63
    const int bc    = (t & 7) * 4;

    #pragma unroll 1
    for (int s = 0; s < NSTEP; s++) {
        const int k0 = s * KB;

        // stage A (128 x 32) transposed to [k][row]: 2 float4 per thread
        #pragma unroll
        for (int i = 0; i < 2; i++) {
            const int row = arow0 + i * 64;
            float4 v = *(const float4*)(xblk + (size_t)row * MDIM + k0 + ac);
            sA[(ac + 0) * LDA + row] = v.x;
            sA[(ac + 1) * LDA + row] = v.y;
            sA[(ac + 2) * LDA + row] = v.z;
            sA[(ac + 3) * LDA + row] = v.w;
        }
        // stage B (64 x 32) transposed to [k][expert]: 1 float4 per thread
        {
            float4 v = *(const float4*)(wblk + (size_t)brow * MDIM + k0 + bc);
            sB[(bc + 0) * LDB + brow] = v.x;
            sB[(bc + 1) * LDB + brow] = v.y;
            sB[(bc + 2) * LDB + brow] = v.z;
            sB[(bc + 3) * LDB + brow] = v.w;
        }
        barc();

        #pragma unroll 8
        for (int kk = 0; kk < KB; kk++) {
            ulonglong2 ap = *(const ulonglong2*)&sA[kk * LDA + ty * 4];
            float4 bv = *(const float4*)&sB[kk * LDB + tx * 4];
            u64 bd[4] = { dup2(bv.x), dup2(bv.y), dup2(bv.z), dup2(bv.w) };
            #pragma unroll
            for (int j = 0; j < 4; j++) {
                ffma2(acc[0][j], ap.x, bd[j]);
                ffma2(acc[1][j], ap.y, bd[j]);
            }
        }
        barc();
    }

    // epilogue: write partial logits [kh][token][expert]
    float* part = g_part + (size_t)kh * S_TOK * NEXP + (size_t)tb * TILE_M * NEXP;
    #pragma unroll
    for (int p = 0; p < 2; p++) {
        const int r0 = ty * 4 + p * 2;
        float4 lo, hi;
        lo.x = __uint_as_float((unsigned)(acc[p][0]));
        lo.y = __uint_as_float((unsigned)(acc[p][1]));
        lo.z = __uint_as_float((unsigned)(acc[p][2]));
        lo.w = __uint_as_float((unsigned)(acc[p][3]));
        hi.x = __uint_as_float((unsigned)(acc[p][0] >> 32));
        hi.y = __uint_as_float((unsigned)(acc[p][1] >> 32));
        hi.z = __uint_as_float((unsigned)(acc[p][2] >> 32));
        hi.w = __uint_as_float((unsigned)(acc[p][3] >> 32));
        *(float4*)&part[(size_t)(r0 + 0) * NEXP + tx * 4] = lo;
        *(float4*)&part[(size_t)(r0 + 1) * NEXP + tx * 4] = hi;
    }
}

// ---------------------------------------------------------------------------
// Kernel 2: reduce K-split partials, softmax/argmax, per-block me/cnt.
// ---------------------------------------------------------------------------
__global__ __launch_bounds__(256) void gate_kernel()
{
    __shared__ float Ls[64 * 65];
    __shared__ int   s_eid[64];
    const int b = blockIdx.x;        // 0..127
    const int t = threadIdx.x;
    const size_t off = (size_t)b * 64 * NEXP;

    #pragma unroll
    for (int i = 0; i < 4; i++) {
        const int idx4 = t + i * 256;     // 0..1023
        float4 v = *(const float4*)&g_part[off + (size_t)idx4 * 4];
        #pragma unroll
        for (int p = 1; p < KSPLIT; p++) {
            float4 w = *(const float4*)&g_part[(size_t)p * S_TOK * NEXP + off + (size_t)idx4 * 4];
            v.x += w.x; v.y += w.y; v.z += w.z; v.w += w.w;
        }
        const int r = (idx4 * 4) >> 6;
        const int e = (idx4 * 4) & 63;
        Ls[r * 65 + e + 0] = v.x;
        Ls[r * 65 + e + 1] = v.y;
        Ls[r * 65 + e + 2] = v.z;
        Ls[r * 65 + e + 3] = v.w;
    }
    __syncthreads();

    if (t < 64) {
        const int r = t;
        float m = -INFINITY; int am = 0;
        #pragma unroll 8
        for (int e = 0; e < NEXP; e++) {
            float v = Ls[r * 65 + e];
            if (v > m) { m = v; am = e; }
        }
        float sum = 0.f;
        #pragma unroll 8
        for (int e = 0; e < NEXP; e++) {
            float ex = expf(Ls[r * 65 + e] - m);
            Ls[r * 65 + e] = ex;
            sum += ex;
        }
        const float inv = 1.f / sum;
        #pragma unroll 8
        for (int e = 0; e < NEXP; e++) Ls[r * 65 + e] *= inv;
        const int s = b * 64 + r;
        g_eid[s]  = am;
        g_gate[s] = inv;
        s_eid[r]  = am;
    }
    __syncthreads();

    if (t < NEXP) {
        const int e = t;
        float msum = 0.f; int cnt = 0;
        #pragma unroll 8
        for (int r = 0; r < 64; r++) {
            msum += Ls[r * 65 + e];
            cnt  += (s_eid[r] == e);
        }
        g_me[b * NEXP + e]  = msum;
        g_cnt[b * NEXP + e] = cnt;
    }
}

// ---------------------------------------------------------------------------
// Kernel 3: exclusive scan over 128 blocks per expert; exp_counts, l_aux.
// ---------------------------------------------------------------------------
__global__ void scan_kernel(float* __restrict__ out)
{
    __shared__ float s_val[NEXP];
    const int e = threadIdx.x;   // 64 threads
    float me_tot = 0.f; int run = 0;
    for (int b = 0; b < NBLK64; b++) {
        g_offs[b * NEXP + e] = run;
        run    += g_cnt[b * NEXP + e];
        me_tot += g_me[b * NEXP + e];
    }
    out[1 + 2 * SEC + e] = (float)run;    // exp_counts (pre-drop)
    s_val[e] = me_tot * (float)run;
    __syncthreads();
    if (e == 0) {
        float acc = 0.f;
        for (int i = 0; i < NEXP; i++) acc += s_val[i];
        out[0] = acc * (1.f / 1048576.f);  // E/S^2 = 64/8192^2
    }
}

// ---------------------------------------------------------------------------
// Kernel 4: resolve in-order rank per token, scatter combine/dispatch.
// ---------------------------------------------------------------------------
__global__ void scatter_kernel(float* __restrict__ out)
{
    __shared__ int   s_eid[64];
    __shared__ float s_g[64];
    const int b = blockIdx.x;
    const int i = threadIdx.x;       // 64 threads
    const int s = b * 64 + i;
    s_eid[i] = g_eid[s];
    s_g[i]   = g_gate[s];
    __syncthreads();
    const int e = s_eid[i];
    int rank = g_offs[b * NEXP + e];
    for (int j = 0; j < i; j++) rank += (s_eid[j] == e);
    if (rank < CAP) {
        size_t base = (size_t)s * (NEXP * CAP) + (size_t)e * CAP + rank;
        out[1 + base]       = s_g[i];   // combine_weights
        out[1 + SEC + base] = 1.0f;     // dispatch_mask
    }
}

// ---------------------------------------------------------------------------
extern "C" void kernel_launch(void* const* d_in, const int* in_sizes, int n_in,
                              void* d_out, int out_size)
{
    const float* x  = (const float*)d_in[0];
    const float* wg = (const float*)d_in[1];
    float* out = (float*)d_out;

    gemm_zero_kernel<<<GRID_G, THREADS>>>(x, wg, out);
    gate_kernel<<<NBLK64, 256>>>();
    scan_kernel<<<1, NEXP>>>(out);
    scatter_kernel<<<NBLK64, 64>>>(out);
}

// round 4
// speedup vs baseline: 1.4726x; 1.4726x over previous
#include <cuda_runtime.h>
#include <cstdint>
#include <math.h>

// Problem constants
#define S_TOK 8192
#define MDIM  4096
#define NEXP  64
#define CAP   128
#define SEC   67108864ULL            // S*E*C
#define OUT_FLOATS 134217793ULL      // 1 + 2*SEC + 64
#define ZMAIN 134217728ULL           // floats zeroed by bulk path (512MB)

// GEMM tiling
#define TILE_M 128                   // tokens per CTA
#define KB     32
#define KSPLIT 2
#define KCHUNK (MDIM / KSPLIT)       // 2048
#define NSTEP  (KCHUNK / KB)         // 64
#define NTB    (S_TOK / TILE_M)      // 64 token blocks
#define GRID_G (NTB * KSPLIT)        // 128 CTAs (1 per SM, balanced)
#define CTHR   256                   // compute threads
#define THREADS (CTHR + 32)          // + 1 TMA-zero warp
#define LDA 132                      // padded smem strides (floats)
#define LDB 68

#define ZCHUNK 16384                 // bytes per bulk store
#define ZPC    256                   // chunks per CTA (128*256*16KB = 512MB)

#define NBLK64 (S_TOK / 64)          // 128 blocks for gate/scatter

typedef unsigned long long u64;

// ---------- scratch (device globals; fully overwritten each launch) ----------
__device__ float g_part[KSPLIT * S_TOK * NEXP];   // 4 MB partial logits
__device__ int   g_eid[S_TOK];
__device__ float g_gate[S_TOK];
__device__ float g_me[NBLK64 * NEXP];
__device__ int   g_cnt[NBLK64 * NEXP];

// packed f32x2 FMA (PTX-only; ptxas never auto-fuses)
__device__ __forceinline__ void ffma2(u64& d, u64 a, u64 b) {
    asm("fma.rn.f32x2 %0, %1, %2, %0;" : "+l"(d) : "l"(a), "l"(b));
}
__device__ __forceinline__ u64 dup2(float b) {
    u64 r; unsigned u = __float_as_uint(b);
    asm("mov.b64 %0, {%1, %1};" : "=l"(r) : "r"(u));
    return r;
}
__device__ __forceinline__ void barc() {   // compute-warps-only barrier
    asm volatile("bar.sync 1, %0;" :: "n"(CTHR) : "memory");
}
__device__ __forceinline__ uint32_t smem_u32(const void* p) {
    uint32_t a;
    asm("{ .reg .u64 t; cvta.to.shared.u64 t, %1; cvt.u32.u64 %0, t; }"
        : "=r"(a) : "l"(p));
    return a;
}

// ---------------------------------------------------------------------------
// Kernel 1: warps 0-7 = 128x64 fp32 GEMM over a K/2 chunk (FFMA2, 4x4 tile,
// register prefetch). Warp 8 = TMA bulk-zero of the 537MB output buffer.
// ---------------------------------------------------------------------------
__global__ __launch_bounds__(THREADS, 1) void gemm_zero_kernel(
    const float* __restrict__ x, const float* __restrict__ wg,
    float* __restrict__ out)
{
    __shared__ float sA[KB * LDA];
    __shared__ float sB[KB * LDB];
    __shared__ alignas(16) float4 zbuf[ZCHUNK / 16];

    const int t  = threadIdx.x;
    const int bx = blockIdx.x;

    // all threads zero the smem staging buffer for the bulk stores
    {
        const float4 z = make_float4(0.f, 0.f, 0.f, 0.f);
        for (int i = t; i < ZCHUNK / 16; i += THREADS) zbuf[i] = z;
    }
    __syncthreads();

    if (t >= CTHR) {
        // ---------------- TMA zero warp ----------------
        const int zt = t - CTHR;
        if (zt == 0) {
            asm volatile("fence.proxy.async.shared::cta;" ::: "memory");
            const uint32_t zaddr = smem_u32(zbuf);
            char* dst = (char*)out + (size_t)bx * (ZPC * (size_t)ZCHUNK);
            #pragma unroll 4
            for (int c = 0; c < ZPC; c++) {
                asm volatile(
                    "cp.async.bulk.global.shared::cta.bulk_group [%0], [%1], %2;"
                    :: "l"(dst + (size_t)c * ZCHUNK), "r"(zaddr), "r"(ZCHUNK)
                    : "memory");
            }
            asm volatile("cp.async.bulk.commit_group;" ::: "memory");
            asm volatile("cp.async.bulk.wait_group 0;" ::: "memory");
        }
        // tail: last 65 floats
        if (bx == 0) {
            for (int i = zt; i < (int)(OUT_FLOATS - ZMAIN); i += 32)
                out[ZMAIN + i] = 0.0f;
        }
        return;
    }

    // ---------------- compute warps ----------------
    const int tb = bx & (NTB - 1);     // token block
    const int kh = bx >> 6;            // k chunk
    const int tx = t & 15;             // col group: 4 experts
    const int ty = t >> 4;             // row group: 8 tokens (4 u64 pairs)

    u64 acc[4][4];
    #pragma unroll
    for (int i = 0; i < 4; i++)
        #pragma unroll
        for (int j = 0; j < 4; j++) acc[i][j] = 0ULL;

    const float* xblk = x  + (size_t)tb * TILE_M * MDIM + (size_t)kh * KCHUNK;
    const float* wblk = wg + (size_t)kh * KCHUNK;

    // staging assignments
    const int arow = t >> 1;           // 0..127
    const int acol = (t & 1) * 16;     // 0 or 16
    const int brow = t >> 2;           // 0..63
    const int bcol = (t & 3) * 8;      // 0,8,16,24

    float4 pa[4], pb[2];
    // prologue: prefetch step 0
    #pragma unroll
    for (int j = 0; j < 4; j++)
        pa[j] = *(const float4*)(xblk + (size_t)arow * MDIM + acol + j * 4);
    #pragma unroll
    for (int j = 0; j < 2; j++)
        pb[j] = *(const float4*)(wblk + (size_t)brow * MDIM + bcol + j * 4);

    #pragma unroll 1
    for (int s = 0; s < NSTEP; s++) {
        // store prefetched tile to smem (transposed to [k][row])
        #pragma unroll
        for (int j = 0; j < 4; j++) {
            sA[(acol + j*4 + 0) * LDA + arow] = pa[j].x;
            sA[(acol + j*4 + 1) * LDA + arow] = pa[j].y;
            sA[(acol + j*4 + 2) * LDA + arow] = pa[j].z;
            sA[(acol + j*4 + 3) * LDA + arow] = pa[j].w;
        }
        #pragma unroll
        for (int j = 0; j < 2; j++) {
            sB[(bcol + j*4 + 0) * LDB + brow] = pb[j].x;
            sB[(bcol + j*4 + 1) * LDB + brow] = pb[j].y;
            sB[(bcol + j*4 + 2) * LDB + brow] = pb[j].z;
            sB[(bcol + j*4 + 3) * LDB + brow] = pb[j].w;
        }
        barc();

        // prefetch next step while computing this one
        if (s + 1 < NSTEP) {
            const int k1 = (s + 1) * KB;
            #pragma unroll
            for (int j = 0; j < 4; j++)
                pa[j] = *(const float4*)(xblk + (size_t)arow * MDIM + k1 + acol + j * 4);
            #pragma unroll
            for (int j = 0; j < 2; j++)
                pb[j] = *(const float4*)(wblk + (size_t)brow * MDIM + k1 + bcol + j * 4);
        }

        // FFMA2 compute: 16 per kk
        #pragma unroll 8
        for (int kk = 0; kk < KB; kk++) {
            ulonglong2 a01 = *(const ulonglong2*)&sA[kk * LDA + ty * 8];
            ulonglong2 a23 = *(const ulonglong2*)&sA[kk * LDA + ty * 8 + 4];
            float4 bv = *(const float4*)&sB[kk * LDB + tx * 4];
            u64 ar[4] = { a01.x, a01.y, a23.x, a23.y };
            u64 bd[4] = { dup2(bv.x), dup2(bv.y), dup2(bv.z), dup2(bv.w) };
            #pragma unroll
            for (int i = 0; i < 4; i++)
                #pragma unroll
                for (int j = 0; j < 4; j++)
                    ffma2(acc[i][j], ar[i], bd[j]);
        }
        barc();
    }

    // epilogue: write partial logits [kh][token][expert]
    float* part = g_part + (size_t)kh * S_TOK * NEXP + (size_t)tb * TILE_M * NEXP;
    #pragma unroll
    for (int i = 0; i < 4; i++) {
        const int r0 = ty * 8 + i * 2;
        float4 lo, hi;
        lo.x = __uint_as_float((unsigned)(acc[i][0]));
        lo.y = __uint_as_float((unsigned)(acc[i][1]));
        lo.z = __uint_as_float((unsigned)(acc[i][2]));
        lo.w = __uint_as_float((unsigned)(acc[i][3]));
        hi.x = __uint_as_float((unsigned)(acc[i][0] >> 32));
        hi.y = __uint_as_float((unsigned)(acc[i][1] >> 32));
        hi.z = __uint_as_float((unsigned)(acc[i][2] >> 32));
        hi.w = __uint_as_float((unsigned)(acc[i][3] >> 32));
        *(float4*)&part[(size_t)(r0 + 0) * NEXP + tx * 4] = lo;
        *(float4*)&part[(size_t)(r0 + 1) * NEXP + tx * 4] = hi;
    }
}

// ---------------------------------------------------------------------------
// Kernel 2: reduce K-split partials, softmax/argmax, per-block me/cnt.
// ---------------------------------------------------------------------------
__global__ __launch_bounds__(256) void gate_kernel()
{
    __shared__ float Ls[64 * 65];
    __shared__ int   s_eid[64];
    const int b = blockIdx.x;        // 0..127
    const int t = threadIdx.x;
    const size_t off = (size_t)b * 64 * NEXP;

    #pragma unroll
    for (int i = 0; i < 4; i++) {
        const int idx4 = t + i * 256;     // 0..1023
        float4 v = *(const float4*)&g_part[off + (size_t)idx4 * 4];
        #pragma unroll
        for (int p = 1; p < KSPLIT; p++) {
            float4 w = *(const float4*)&g_part[(size_t)p * S_TOK * NEXP + off + (size_t)idx4 * 4];
            v.x += w.x; v.y += w.y; v.z += w.z; v.w += w.w;
        }
        const int r = (idx4 * 4) >> 6;
        const int e = (idx4 * 4) & 63;
        Ls[r * 65 + e + 0] = v.x;
        Ls[r * 65 + e + 1] = v.y;
        Ls[r * 65 + e + 2] = v.z;
        Ls[r * 65 + e + 3] = v.w;
    }
    __syncthreads();

    if (t < 64) {
        const int r = t;
        float m = -INFINITY; int am = 0;
        #pragma unroll 8
        for (int e = 0; e < NEXP; e++) {
            float v = Ls[r * 65 + e];
            if (v > m) { m = v; am = e; }
        }
        float sum = 0.f;
        #pragma unroll 8
        for (int e = 0; e < NEXP; e++) {
            float ex = expf(Ls[r * 65 + e] - m);
            Ls[r * 65 + e] = ex;
            sum += ex;
        }
        const float inv = 1.f / sum;
        #pragma unroll 8
        for (int e = 0; e < NEXP; e++) Ls[r * 65 + e] *= inv;
        const int s = b * 64 + r;
        g_eid[s]  = am;
        g_gate[s] = inv;
        s_eid[r]  = am;
    }
    __syncthreads();

    if (t < NEXP) {
        const int e = t;
        float msum = 0.f; int cnt = 0;
        #pragma unroll 8
        for (int r = 0; r < 64; r++) {
            msum += Ls[r * 65 + e];
            cnt  += (s_eid[r] == e);
        }
        g_me[b * NEXP + e]  = msum;
        g_cnt[b * NEXP + e] = cnt;
    }
}

// ---------------------------------------------------------------------------
// Kernel 3: fused offs+rank+scatter (match_any rank). Block 0 also emits
// exp_counts and l_aux.
// ---------------------------------------------------------------------------
__global__ __launch_bounds__(64) void scatter_kernel(float* __restrict__ out)
{
    __shared__ int cnt0[NEXP];
    const int b = blockIdx.x;
    const int i = threadIdx.x;       // 0..63
    const int s = b * 64 + i;
    const int e = g_eid[s];
    const float g = g_gate[s];

    // expert offset from preceding blocks (L2-hot g_cnt)
    int offs = 0;
    #pragma unroll 4
    for (int bp = 0; bp < b; bp++) offs += g_cnt[bp * NEXP + e];

    // warp-local rank via match
    cnt0[i] = 0;
    __syncthreads();
    const unsigned mm = __match_any_sync(0xFFFFFFFFu, e);
    const int lane = i & 31;
    int rank_w = __popc(mm & ((1u << lane) - 1u));
    if (i < 32) {
        if (lane == __ffs(mm) - 1) cnt0[e] = __popc(mm);  // warp0 histogram
    }
    __syncthreads();
    if (i >= 32) rank_w += cnt0[e];

    const int rank = offs + rank_w;
    if (rank < CAP) {
        size_t base = (size_t)s * (NEXP * CAP) + (size_t)e * CAP + rank;
        out[1 + base]       = g;      // combine_weights
        out[1 + SEC + base] = 1.0f;   // dispatch_mask
    }

    // block 0: exp_counts + l_aux
    if (b == 0) {
        __shared__ float s_val[NEXP];
        const int ee = i;   // 64 threads, one expert each
        float me_tot = 0.f; int run = 0;
        #pragma unroll 4
        for (int bp = 0; bp < NBLK64; bp++) {
            run    += g_cnt[bp * NEXP + ee];
            me_tot += g_me[bp * NEXP + ee];
        }
        out[1 + 2 * SEC + ee] = (float)run;     // exp_counts (pre-drop)
        s_val[ee] = me_tot * (float)run;
        __syncthreads();
        if (ee == 0) {
            float acc = 0.f;
            for (int k = 0; k < NEXP; k++) acc += s_val[k];
            out[0] = acc * (1.f / 1048576.f);   // E/S^2 = 64/8192^2
        }
    }
}

// ---------------------------------------------------------------------------
extern "C" void kernel_launch(void* const* d_in, const int* in_sizes, int n_in,
                              void* d_out, int out_size)
{
    const float* x  = (const float*)d_in[0];
    const float* wg = (const float*)d_in[1];
    float* out = (float*)d_out;

    gemm_zero_kernel<<<GRID_G, THREADS>>>(x, wg, out);
    gate_kernel<<<NBLK64, 256>>>();
    scatter_kernel<<<NBLK64, 64>>>(out);
}